// round 2
// baseline (speedup 1.0000x reference)
#include <cuda_runtime.h>
#include <cuda_bf16.h>

#define B_  256
#define N_  512
#define F_  128
#define E_  4

// Scratch: h[b,e,n,u] (256 MiB) and out2[b,n,u] (64 MiB)
__device__ float g_h[(size_t)B_ * E_ * N_ * F_];
__device__ float g_o2[(size_t)B_ * N_ * F_];

// ---------- packed f32x2 helpers (sm_100+) ----------
__device__ __forceinline__ unsigned long long ffma2(unsigned long long a,
                                                    unsigned long long b,
                                                    unsigned long long c) {
    unsigned long long d;
    asm("fma.rn.f32x2 %0, %1, %2, %3;" : "=l"(d) : "l"(a), "l"(b), "l"(c));
    return d;
}
__device__ __forceinline__ unsigned long long pack2s(float a) {
    unsigned long long r;
    asm("mov.b64 %0, {%1, %1};" : "=l"(r) : "f"(a));
    return r;
}
__device__ __forceinline__ float2 unpack2(unsigned long long v) {
    float2 r;
    asm("mov.b64 {%0, %1}, %2;" : "=f"(r.x), "=f"(r.y) : "l"(v));
    return r;
}

// Shared tile buffers (double-buffered)
struct Tiles {
    float As[2][16][132];   // As[s][k][m], m fast, padded to kill conflicts
    float Bs[2][16][128];   // Bs[s][k][n]
};

// ---------- global -> register prefetch of one 128x16 A tile + 16x128 B tile ----
__device__ __forceinline__ void tile_fetch(const float* __restrict__ Aptr, int lda,
                                           const float* __restrict__ Bptr, int ldb,
                                           float4 av[2], float4 bv[2], int tid) {
#pragma unroll
    for (int it = 0; it < 2; ++it) {
        int f   = tid + it * 256;      // 0..511 float4s
        int row = f >> 2;              // A: 4 float4 per row
        int c4  = (f & 3) * 4;
        av[it] = *(const float4*)(Aptr + (size_t)row * lda + c4);
        int kk = f >> 5;               // B: 32 float4 per row
        int n4 = (f & 31) * 4;
        bv[it] = *(const float4*)(Bptr + (size_t)kk * ldb + n4);
    }
}

// ---------- register -> smem store of a prefetched tile ----------
__device__ __forceinline__ void tile_store(float (*As)[132], float (*Bs)[128],
                                           const float4 av[2], const float4 bv[2],
                                           int tid) {
#pragma unroll
    for (int it = 0; it < 2; ++it) {
        int f   = tid + it * 256;
        int row = f >> 2;
        int c4  = (f & 3) * 4;
        As[c4 + 0][row] = av[it].x;
        As[c4 + 1][row] = av[it].y;
        As[c4 + 2][row] = av[it].z;
        As[c4 + 3][row] = av[it].w;
        int kk = f >> 5;
        int n4 = (f & 31) * 4;
        *(float4*)&Bs[kk][n4] = bv[it];
    }
}

// ---------- 16-k compute step on one smem buffer ----------
__device__ __forceinline__ void tile_compute(const float (*As)[132],
                                             const float (*Bs)[128],
                                             unsigned long long acc[8][4],
                                             int tx, int ty) {
#pragma unroll
    for (int k = 0; k < 16; ++k) {
        float4 a0 = *(const float4*)&As[k][ty * 8];
        float4 a1 = *(const float4*)&As[k][ty * 8 + 4];
        const unsigned long long* bp = (const unsigned long long*)&Bs[k][tx * 8];
        unsigned long long b0 = bp[0], b1 = bp[1], b2 = bp[2], b3 = bp[3];
        float am[8] = {a0.x, a0.y, a0.z, a0.w, a1.x, a1.y, a1.z, a1.w};
#pragma unroll
        for (int i = 0; i < 8; ++i) {
            unsigned long long ap = pack2s(am[i]);
            acc[i][0] = ffma2(ap, b0, acc[i][0]);
            acc[i][1] = ffma2(ap, b1, acc[i][1]);
            acc[i][2] = ffma2(ap, b2, acc[i][2]);
            acc[i][3] = ffma2(ap, b3, acc[i][3]);
        }
    }
}

// ---------- Kernel 1: projections ----------
// blockIdx.x: 1024 row-tiles of [B*N, F]; blockIdx.y: e in 0..4 (4 == W2/b2 path)
__global__ __launch_bounds__(256, 2) void k_proj(const float* __restrict__ n_t,
                                                 const float* __restrict__ W_adj,
                                                 const float* __restrict__ b_adj,
                                                 const float* __restrict__ W2,
                                                 const float* __restrict__ b2) {
    __shared__ Tiles tiles;

    int tid = threadIdx.x;
    int tx  = tid & 15;
    int ty  = tid >> 4;

    int t  = blockIdx.x;           // 0..1023
    int e  = blockIdx.y;           // 0..4
    int b  = t >> 2;
    int n0 = (t & 3) << 7;

    const float* Aorg = n_t + ((size_t)b * N_ + n0) * F_;
    const float* W    = (e < 4) ? (W_adj + (size_t)e * F_ * F_) : W2;
    const float* bias = (e < 4) ? (b_adj + e * F_) : b2;
    float* Out        = (e < 4) ? (g_h + (((size_t)b * E_ + e) * N_ + n0) * F_)
                                : (g_o2 + ((size_t)b * N_ + n0) * F_);

    unsigned long long acc[8][4];
#pragma unroll
    for (int i = 0; i < 8; ++i)
#pragma unroll
        for (int j = 0; j < 4; ++j) acc[i][j] = 0ull;

    const int NK = F_ / 16;   // 8 k-tiles

    float4 av[2], bv[2];
    tile_fetch(Aorg, F_, W, F_, av, bv, tid);
    tile_store(tiles.As[0], tiles.Bs[0], av, bv, tid);
    __syncthreads();

    for (int kc = 0; kc < NK; ++kc) {
        int p = kc & 1;
        if (kc + 1 < NK)
            tile_fetch(Aorg + (kc + 1) * 16, F_,
                       W + (size_t)(kc + 1) * 16 * F_, F_, av, bv, tid);
        tile_compute(tiles.As[p], tiles.Bs[p], acc, tx, ty);
        if (kc + 1 < NK) {
            tile_store(tiles.As[p ^ 1], tiles.Bs[p ^ 1], av, bv, tid);
            __syncthreads();
        }
    }

    float bvv[8];
#pragma unroll
    for (int j = 0; j < 8; ++j) bvv[j] = bias[tx * 8 + j];

#pragma unroll
    for (int i = 0; i < 8; ++i) {
        int row = ty * 8 + i;
        float o[8];
#pragma unroll
        for (int j = 0; j < 4; ++j) {
            float2 p2 = unpack2(acc[i][j]);
            o[2 * j]     = p2.x + bvv[2 * j];
            o[2 * j + 1] = p2.y + bvv[2 * j + 1];
        }
        float* dst = Out + (size_t)row * F_ + tx * 8;
        *(float4*)(dst)     = make_float4(o[0], o[1], o[2], o[3]);
        *(float4*)(dst + 4) = make_float4(o[4], o[5], o[6], o[7]);
    }
}

// ---------- Kernel 2: message passing + epilogue ----------
// blockIdx.x: 4 row-tiles of N; blockIdx.y: b
// K loop is flattened over (e, kc): 4 * 32 = 128 k-tiles of 16.
__global__ __launch_bounds__(256, 2) void k_msg(const float* __restrict__ adj,
                                                float* __restrict__ out) {
    __shared__ Tiles tiles;

    int tid = threadIdx.x;
    int tx  = tid & 15;
    int ty  = tid >> 4;

    int mt = blockIdx.x;
    int b  = blockIdx.y;
    int n0 = mt << 7;

    unsigned long long acc[8][4];
#pragma unroll
    for (int i = 0; i < 8; ++i)
#pragma unroll
        for (int j = 0; j < 4; ++j) acc[i][j] = 0ull;

    const float* Abase = adj + (((size_t)b * E_) * N_ + n0) * N_;  // e stride: N_*N_
    const float* Bbase = g_h + (((size_t)b * E_) * N_) * F_;       // e stride: N_*F_

    const int NKE = N_ / 16;          // 32 k-tiles per edge type
    const int NKT = E_ * NKE;         // 128 total

    float4 av[2], bv[2];
    tile_fetch(Abase, N_, Bbase, F_, av, bv, tid);
    tile_store(tiles.As[0], tiles.Bs[0], av, bv, tid);
    __syncthreads();

    for (int kt = 0; kt < NKT; ++kt) {
        int p = kt & 1;
        if (kt + 1 < NKT) {
            int e  = (kt + 1) >> 5;          // / NKE
            int kc = (kt + 1) & 31;          // % NKE
            const float* Aptr = Abase + (size_t)e * N_ * N_ + kc * 16;
            const float* Bptr = Bbase + (size_t)e * N_ * F_ + (size_t)kc * 16 * F_;
            tile_fetch(Aptr, N_, Bptr, F_, av, bv, tid);
        }
        tile_compute(tiles.As[p], tiles.Bs[p], acc, tx, ty);
        if (kt + 1 < NKT) {
            tile_store(tiles.As[p ^ 1], tiles.Bs[p ^ 1], av, bv, tid);
            __syncthreads();
        }
    }

    const float* o2 = g_o2 + ((size_t)b * N_ + n0) * F_;
    float* O        = out + ((size_t)b * N_ + n0) * F_;

#pragma unroll
    for (int i = 0; i < 8; ++i) {
        int row = ty * 8 + i;
        const float* o2r = o2 + (size_t)row * F_ + tx * 8;
        float4 c0 = *(const float4*)(o2r);
        float4 c1 = *(const float4*)(o2r + 4);
        float cc[8] = {c0.x, c0.y, c0.z, c0.w, c1.x, c1.y, c1.z, c1.w};
        float o[8];
#pragma unroll
        for (int j = 0; j < 4; ++j) {
            float2 p2 = unpack2(acc[i][j]);
            o[2 * j]     = tanhf(p2.x + cc[2 * j]);
            o[2 * j + 1] = tanhf(p2.y + cc[2 * j + 1]);
        }
        float* dst = O + (size_t)row * F_ + tx * 8;
        *(float4*)(dst)     = make_float4(o[0], o[1], o[2], o[3]);
        *(float4*)(dst + 4) = make_float4(o[4], o[5], o[6], o[7]);
    }
}

extern "C" void kernel_launch(void* const* d_in, const int* in_sizes, int n_in,
                              void* d_out, int out_size) {
    const float* n_t   = (const float*)d_in[0];
    const float* adj   = (const float*)d_in[1];
    const float* W_adj = (const float*)d_in[2];
    const float* b_adj = (const float*)d_in[3];
    const float* W2    = (const float*)d_in[4];
    const float* b2    = (const float*)d_in[5];
    float* out = (float*)d_out;

    // 5 projection GEMMs (e=0..3 -> W_adj/b_adj, e=4 -> W2/b2)
    k_proj<<<dim3(1024, 5), 256>>>(n_t, W_adj, b_adj, W2, b2);
    // message passing + sum over e + tanh epilogue
    k_msg<<<dim3(4, 256), 256>>>(adj, out);
}

// round 15
// speedup vs baseline: 2.3191x; 2.3191x over previous
#include <cuda_runtime.h>
#include <cuda_fp16.h>
#include <cstdint>

#define B_  256
#define N_  512
#define F_  128
#define E_  4

// f16 split scratch: hT[(b*E+e)][u][m] (hi/lo), W2T[u][i] (hi/lo)
__device__ __half g_hT_hi[(size_t)B_ * E_ * F_ * N_];
__device__ __half g_hT_lo[(size_t)B_ * E_ * F_ * N_];
__device__ __half g_W2T_hi[F_ * F_];
__device__ __half g_W2T_lo[F_ * F_];

// ===================== helpers =====================
__device__ __forceinline__ uint32_t smem_u32(const void* p) {
    uint32_t a;
    asm("{ .reg .u64 t; cvta.to.shared.u64 t, %1; cvt.u32.u64 %0, t; }" : "=r"(a) : "l"(p));
    return a;
}
__device__ __forceinline__ void ldsm_x4(uint32_t addr, uint32_t r[4]) {
    asm volatile("ldmatrix.sync.aligned.m8n8.x4.shared.b16 {%0,%1,%2,%3}, [%4];"
                 : "=r"(r[0]), "=r"(r[1]), "=r"(r[2]), "=r"(r[3]) : "r"(addr));
}
__device__ __forceinline__ void mma16816(float d[4], const uint32_t a[4],
                                         uint32_t b0, uint32_t b1) {
    asm volatile("mma.sync.aligned.m16n8k16.row.col.f32.f16.f16.f32 "
                 "{%0,%1,%2,%3}, {%4,%5,%6,%7}, {%8,%9}, {%0,%1,%2,%3};"
                 : "+f"(d[0]), "+f"(d[1]), "+f"(d[2]), "+f"(d[3])
                 : "r"(a[0]), "r"(a[1]), "r"(a[2]), "r"(a[3]), "r"(b0), "r"(b1));
}
__device__ __forceinline__ void cp16(uint32_t dst, const void* src) {
    asm volatile("cp.async.cg.shared.global [%0], [%1], 16;" :: "r"(dst), "l"(src));
}
__device__ __forceinline__ void cp_commit() { asm volatile("cp.async.commit_group;" ::: "memory"); }
__device__ __forceinline__ void cp_wait0()  { asm volatile("cp.async.wait_group 0;" ::: "memory"); }

// split one float4 into two half2-pairs (hi) and residual (lo)
__device__ __forceinline__ void split_f4(float4 v, uint2& hi, uint2& lo) {
    __half2 h0 = __floats2half2_rn(v.x, v.y);
    __half2 h1 = __floats2half2_rn(v.z, v.w);
    float2 f0 = __half22float2(h0);
    float2 f1 = __half22float2(h1);
    __half2 l0 = __floats2half2_rn(v.x - f0.x, v.y - f0.y);
    __half2 l1 = __floats2half2_rn(v.z - f1.x, v.w - f1.y);
    hi = make_uint2(*(unsigned*)&h0, *(unsigned*)&h1);
    lo = make_uint2(*(unsigned*)&l0, *(unsigned*)&l1);
}

// 16-k mma block: A (hi,lo) and B (hi,lo) tiles in smem, 3-pass split accumulation.
// Warp tile: 32 (M) x 64 (N). acc[mt][j8][4].
template <int PITCH>
__device__ __forceinline__ void mma_block(uint32_t aHi, uint32_t aLo,
                                          uint32_t bHi, uint32_t bLo,
                                          int kk, int wm, int wn, int lane,
                                          float acc[2][8][4]) {
    uint32_t ah[2][4], al[2][4], bh[4][4], bl[4][4];
    int arow = lane & 15, acol = (lane >> 4) * 16;
#pragma unroll
    for (int mt = 0; mt < 2; ++mt) {
        uint32_t off = (uint32_t)(wm * 32 + mt * 16 + arow) * PITCH + kk * 32 + acol;
        ldsm_x4(aHi + off, ah[mt]);
        ldsm_x4(aLo + off, al[mt]);
    }
    int brow = (lane >> 4) * 8 + (lane & 7), bcol = ((lane >> 3) & 1) * 16;
#pragma unroll
    for (int j = 0; j < 4; ++j) {
        uint32_t off = (uint32_t)(wn * 64 + j * 16 + brow) * PITCH + kk * 32 + bcol;
        ldsm_x4(bHi + off, bh[j]);
        ldsm_x4(bLo + off, bl[j]);
    }
#pragma unroll
    for (int mt = 0; mt < 2; ++mt)
#pragma unroll
        for (int j = 0; j < 4; ++j)
#pragma unroll
            for (int h = 0; h < 2; ++h) {
                float* d = acc[mt][j * 2 + h];
                mma16816(d, ah[mt], bh[j][2 * h], bh[j][2 * h + 1]);
                mma16816(d, ah[mt], bl[j][2 * h], bl[j][2 * h + 1]);
                mma16816(d, al[mt], bh[j][2 * h], bh[j][2 * h + 1]);
            }
}

// ===================== k_w2t: W2 [i][u] -> W2T split [u][i] =====================
__global__ void k_w2t(const float* __restrict__ W2) {
    int t = threadIdx.x;
    int u = t >> 1, ih = t & 1;
#pragma unroll
    for (int ii = 0; ii < 64; ii += 2) {
        int i0 = ih * 64 + ii;
        float a = W2[(size_t)i0 * F_ + u];
        float b = W2[(size_t)(i0 + 1) * F_ + u];
        __half2 h = __floats2half2_rn(a, b);
        float2 hf = __half22float2(h);
        __half2 l = __floats2half2_rn(a - hf.x, b - hf.y);
        *(unsigned*)(g_W2T_hi + (size_t)u * F_ + i0) = *(unsigned*)&h;
        *(unsigned*)(g_W2T_lo + (size_t)u * F_ + i0) = *(unsigned*)&l;
    }
}

// ===================== k_proj =====================
// hT[u][m] = sum_i W_e^T[u][i] * n[m][i] + b_e[u], output f16 hi/lo.
// M-dim = u (128), N-dim = m (128 tile), K = i (128, fully resident).
#define PJ_PITCH 272                      // bytes per smem row (136 halves), 16B-aligned
#define PJ_TILE  (128 * PJ_PITCH)         // 34816
#define PJ_SMEM  (4 * PJ_TILE)            // 139264

__global__ void __launch_bounds__(256, 1)
k_proj(const float* __restrict__ n_t, const float* __restrict__ W_adj,
       const float* __restrict__ b_adj) {
    extern __shared__ char smem[];
    uint32_t sb = smem_u32(smem);
    int tid = threadIdx.x, lane = tid & 31, wid = tid >> 5;
    int wm = wid & 3, wn = wid >> 2;

    int bx = blockIdx.x;
    int mt_ = bx & 3, e = (bx >> 2) & 3, b = bx >> 4;
    int m0 = mt_ * 128;

    // A = W^T split: read W[i][u] coalesced, store transposed [u][i]
    const float* W = W_adj + (size_t)e * F_ * F_;
    for (int rep = 0; rep < 64; ++rep) {
        int idx = tid + rep * 256;
        int i = idx >> 7, u = idx & 127;
        float w = W[(size_t)i * F_ + u];
        __half hh = __float2half_rn(w);
        __half hl = __float2half_rn(w - __half2float(hh));
        *(__half*)(smem + 0 * PJ_TILE + u * PJ_PITCH + i * 2) = hh;
        *(__half*)(smem + 1 * PJ_TILE + u * PJ_PITCH + i * 2) = hl;
    }
    // B = n_t slab split: [m][i]
    const float* Bsrc = n_t + ((size_t)b * N_ + m0) * F_;
    for (int rep = 0; rep < 16; ++rep) {
        int f = tid + rep * 256;
        int row = f >> 5, c4 = (f & 31) << 2;
        float4 v = *(const float4*)(Bsrc + (size_t)row * F_ + c4);
        uint2 hi, lo;
        split_f4(v, hi, lo);
        *(uint2*)(smem + 2 * PJ_TILE + row * PJ_PITCH + c4 * 2) = hi;
        *(uint2*)(smem + 3 * PJ_TILE + row * PJ_PITCH + c4 * 2) = lo;
    }
    __syncthreads();

    float acc[2][8][4];
#pragma unroll
    for (int i = 0; i < 2; ++i)
#pragma unroll
        for (int j = 0; j < 8; ++j)
#pragma unroll
            for (int k = 0; k < 4; ++k) acc[i][j][k] = 0.f;

#pragma unroll
    for (int kk = 0; kk < 8; ++kk)
        mma_block<PJ_PITCH>(sb, sb + PJ_TILE, sb + 2 * PJ_TILE, sb + 3 * PJ_TILE,
                            kk, wm, wn, lane, acc);

    // epilogue: +bias, split f16, store to g_hT [u][m]
    size_t hbase = (size_t)(b * 4 + e) * F_ * N_;
#pragma unroll
    for (int mt = 0; mt < 2; ++mt) {
        int u0 = wm * 32 + mt * 16 + (lane >> 2);
        float bia0 = b_adj[e * F_ + u0];
        float bia1 = b_adj[e * F_ + u0 + 8];
#pragma unroll
        for (int j8 = 0; j8 < 8; ++j8) {
            int col = m0 + wn * 64 + j8 * 8 + (lane & 3) * 2;
            float* d = acc[mt][j8];
            float x0 = d[0] + bia0, x1 = d[1] + bia0;
            float y0 = d[2] + bia1, y1 = d[3] + bia1;
            __half2 h0 = __floats2half2_rn(x0, x1);
            float2 f0 = __half22float2(h0);
            __half2 l0 = __floats2half2_rn(x0 - f0.x, x1 - f0.y);
            __half2 h1 = __floats2half2_rn(y0, y1);
            float2 f1 = __half22float2(h1);
            __half2 l1 = __floats2half2_rn(y0 - f1.x, y1 - f1.y);
            *(__half2*)(g_hT_hi + hbase + (size_t)u0 * N_ + col) = h0;
            *(__half2*)(g_hT_lo + hbase + (size_t)u0 * N_ + col) = l0;
            *(__half2*)(g_hT_hi + hbase + (size_t)(u0 + 8) * N_ + col) = h1;
            *(__half2*)(g_hT_lo + hbase + (size_t)(u0 + 8) * N_ + col) = l1;
        }
    }
}

// ===================== k_msg =====================
// out[n][u] = tanh( sum_e adj_e[n][m] hT_e[u][m]^T + n_t[n][i] W2T[u][i]^T + b2[u] )
// M-dim = n (128 tile), N-dim = u (128), K = 4*512 + 128 in 34 chunks of 64.
#define MS_PITCH 144
#define MS_TILE  (128 * MS_PITCH)         // 18432
#define MS_STAGE (4 * MS_TILE)            // 73728: AHI, ALO, BHI, BLO
#define MS_SMEM  (2 * MS_STAGE)           // 147456
#define MS_NC    34

__global__ void __launch_bounds__(256, 1)
k_msg(const float* __restrict__ adj, const float* __restrict__ n_t,
      const float* __restrict__ b2, float* __restrict__ out) {
    extern __shared__ char smem[];
    uint32_t sb = smem_u32(smem);
    int tid = threadIdx.x, lane = tid & 31, wid = tid >> 5;
    int wm = wid & 3, wn = wid >> 2;

    int b = blockIdx.x >> 2;
    int n0 = (blockIdx.x & 3) * 128;

    float acc[2][8][4];
#pragma unroll
    for (int i = 0; i < 2; ++i)
#pragma unroll
        for (int j = 0; j < 8; ++j)
#pragma unroll
            for (int k = 0; k < 4; ++k) acc[i][j][k] = 0.f;

    const float* Ap;
    const __half *Bh, *Bl;
    int astr, bstr;

    // ---- chunk source resolver ----
#define SRCS(c)                                                                  \
    do {                                                                         \
        int _c = (c);                                                            \
        if (_c < 32) {                                                           \
            int _e = _c >> 3, _mo = (_c & 7) * 64;                               \
            Ap = adj + (((size_t)(b * 4 + _e)) * N_ + n0) * N_ + _mo;            \
            astr = N_;                                                           \
            size_t _ho = (size_t)(b * 4 + _e) * F_ * N_ + _mo;                   \
            Bh = g_hT_hi + _ho; Bl = g_hT_lo + _ho; bstr = N_;                   \
        } else {                                                                 \
            int _k0 = (_c - 32) * 64;                                            \
            Ap = n_t + ((size_t)b * N_ + n0) * F_ + _k0;                         \
            astr = F_;                                                           \
            Bh = g_W2T_hi + _k0; Bl = g_W2T_lo + _k0; bstr = F_;                 \
        }                                                                        \
    } while (0)

#define ISSUE_B(so)                                                              \
    do {                                                                         \
        _Pragma("unroll")                                                        \
        for (int r = 0; r < 4; ++r) {                                            \
            int t = tid + r * 256;                                               \
            int row = t >> 3, seg = t & 7;                                       \
            uint32_t d = sb + (so) + 2 * MS_TILE + row * MS_PITCH + seg * 16;    \
            cp16(d, Bh + (size_t)row * bstr + seg * 8);                          \
            cp16(d + MS_TILE, Bl + (size_t)row * bstr + seg * 8);                \
        }                                                                        \
        cp_commit();                                                             \
    } while (0)

#define LOAD_A()                                                                 \
    do {                                                                         \
        _Pragma("unroll")                                                        \
        for (int r = 0; r < 8; ++r) {                                            \
            int f = tid + r * 256;                                               \
            int row = f >> 4, c4 = (f & 15) << 2;                                \
            av[r] = *(const float4*)(Ap + (size_t)row * astr + c4);              \
        }                                                                        \
    } while (0)

#define STORE_A(so)                                                              \
    do {                                                                         \
        _Pragma("unroll")                                                        \
        for (int r = 0; r < 8; ++r) {                                            \
            int f = tid + r * 256;                                               \
            int row = f >> 4, c4 = (f & 15) << 2;                                \
            uint2 hi, lo;                                                        \
            split_f4(av[r], hi, lo);                                             \
            *(uint2*)(smem + (so) + row * MS_PITCH + c4 * 2) = hi;               \
            *(uint2*)(smem + (so) + MS_TILE + row * MS_PITCH + c4 * 2) = lo;     \
        }                                                                        \
    } while (0)

    float4 av[8];
    SRCS(0);
    ISSUE_B(0);
    LOAD_A();
    STORE_A(0);
    cp_wait0();
    __syncthreads();

    for (int c = 0; c < MS_NC; ++c) {
        int so = (c & 1) * MS_STAGE;
        int sn = so ^ MS_STAGE;
        bool more = (c + 1 < MS_NC);
        if (more) {
            SRCS(c + 1);
            ISSUE_B(sn);
            LOAD_A();
        }
#pragma unroll
        for (int kk = 0; kk < 4; ++kk)
            mma_block<MS_PITCH>(sb + so, sb + so + MS_TILE,
                                sb + so + 2 * MS_TILE, sb + so + 3 * MS_TILE,
                                kk, wm, wn, lane, acc);
        if (more) STORE_A(sn);
        cp_wait0();
        __syncthreads();
    }

    // epilogue: tanh(acc + b2), store out[b][n][u]
#pragma unroll
    for (int mt = 0; mt < 2; ++mt) {
        int row = wm * 32 + mt * 16 + (lane >> 2);
        int n = n0 + row;
#pragma unroll
        for (int j8 = 0; j8 < 8; ++j8) {
            int col = wn * 64 + j8 * 8 + (lane & 3) * 2;
            float2 b2c = *(const float2*)&b2[col];
            float* d = acc[mt][j8];
            float2 o0 = make_float2(tanhf(d[0] + b2c.x), tanhf(d[1] + b2c.y));
            float2 o1 = make_float2(tanhf(d[2] + b2c.x), tanhf(d[3] + b2c.y));
            *(float2*)(out + ((size_t)(b * N_ + n)) * F_ + col) = o0;
            *(float2*)(out + ((size_t)(b * N_ + n + 8)) * F_ + col) = o1;
        }
    }
}

// ===================== launch =====================
extern "C" void kernel_launch(void* const* d_in, const int* in_sizes, int n_in,
                              void* d_out, int out_size) {
    const float* n_t   = (const float*)d_in[0];
    const float* adj   = (const float*)d_in[1];
    const float* W_adj = (const float*)d_in[2];
    const float* b_adj = (const float*)d_in[3];
    const float* W2    = (const float*)d_in[4];
    const float* b2    = (const float*)d_in[5];
    float* out = (float*)d_out;

    cudaFuncSetAttribute(k_proj, cudaFuncAttributeMaxDynamicSharedMemorySize, PJ_SMEM);
    cudaFuncSetAttribute(k_msg,  cudaFuncAttributeMaxDynamicSharedMemorySize, MS_SMEM);

    k_w2t<<<1, 256>>>(W2);
    k_proj<<<B_ * 16, 256, PJ_SMEM>>>(n_t, W_adj, b_adj);
    k_msg<<<B_ * 4, 256, MS_SMEM>>>(adj, n_t, b2, out);
}